// round 1
// baseline (speedup 1.0000x reference)
#include <cuda_runtime.h>
#include <cstdint>

// Problem constants
#define BB 64
#define CC 21
#define LL 1024
#define DM 768
#define PL 16
#define ST 8
#define NSEQ (BB * CC)            // 1344
#define PTOK 128                  // patches per sequence
#define MTOT (NSEQ * PTOK)        // 172032 tokens
#define KCONV 48                  // PATCH_LEN * 3

// Scratch (static device allocations are allowed; cudaMalloc is not)
__device__ float g_emb[(size_t)MTOT * DM];   // 528 MB
__device__ float g_h1[(size_t)MTOT * DM];    // 528 MB
__device__ float g_wT[KCONV * DM];           // conv_w transposed to [k][d]

// ---------------- packed f32x2 helpers ----------------
__device__ __forceinline__ void fma2(unsigned long long& acc,
                                     unsigned long long a,
                                     unsigned long long b) {
    asm volatile("fma.rn.f32x2 %0, %1, %2, %0;" : "+l"(acc) : "l"(a), "l"(b));
}
__device__ __forceinline__ unsigned long long pack2(float x, float y) {
    unsigned long long r;
    asm("mov.b64 %0, {%1, %2};" : "=l"(r) : "f"(x), "f"(y));
    return r;
}
__device__ __forceinline__ float2 unpack2(unsigned long long v) {
    float2 f;
    asm("mov.b64 {%0, %1}, %2;" : "=f"(f.x), "=f"(f.y) : "l"(v));
    return f;
}

// one K-step of the 8x8 micro-tile (4 packed column-pairs)
__device__ __forceinline__ void mm_step(const float* __restrict__ asrow,
                                        const float* __restrict__ bsrow,
                                        int ty, int tx,
                                        unsigned long long (&acc)[8][4]) {
    float4 a03 = *(const float4*)(asrow + ty * 8);
    float4 a47 = *(const float4*)(asrow + ty * 8 + 4);
    unsigned long long bb[4];
#pragma unroll
    for (int q = 0; q < 4; q++)
        bb[q] = *(const unsigned long long*)(bsrow + tx * 8 + 2 * q);
    float av[8] = {a03.x, a03.y, a03.z, a03.w, a47.x, a47.y, a47.z, a47.w};
#pragma unroll
    for (int i = 0; i < 8; i++) {
        unsigned long long a2 = pack2(av[i], av[i]);
#pragma unroll
        for (int q = 0; q < 4; q++) fma2(acc[i][q], a2, bb[q]);
    }
}

// ---------------- kernel 0: transpose conv_w (DM,PL,3) -> wT[k=t*16+i][d] ----------------
__global__ void k_transpose_w(const float* __restrict__ conv_w) {
    int gid = blockIdx.x * blockDim.x + threadIdx.x;
    if (gid >= KCONV * DM) return;
    int k = gid / DM;
    int d = gid - k * DM;
    int i = k & 15;
    int t = k >> 4;
    g_wT[gid] = conv_w[d * KCONV + i * 3 + t];
}

// ---------------- kernel 1: patch gather + conv-embed GEMM (M x 768, K=48) ----------------
__global__ void __launch_bounds__(256) k_embed(const float* __restrict__ x) {
    __shared__ __align__(16) float As[16][132];
    __shared__ __align__(16) float Bs[16][132];
    int tid = threadIdx.x;
    int tx = tid & 15, ty = tid >> 4;
    int m0 = blockIdx.y << 7;
    int n0 = blockIdx.x << 7;

    unsigned long long acc[8][4];
#pragma unroll
    for (int i = 0; i < 8; i++)
#pragma unroll
        for (int q = 0; q < 4; q++) acc[i][q] = 0ULL;

#pragma unroll
    for (int kt = 0; kt < 3; kt++) {  // kt == t (conv tap)
        __syncthreads();
        // gather A tile: 128 tokens x 16 patch elements for tap t=kt
#pragma unroll
        for (int it = 0; it < 8; it++) {
            int e = tid + it * 256;       // 0..2047
            int k16 = e & 15;             // i within patch
            int ml = e >> 4;              // local token
            int m = m0 + ml;
            int n = m >> 7;
            int p = m & 127;
            int pp = (p + kt + 127) & 127;   // circular neighbor (p + t - 1) mod 128
            int j = (pp << 3) + k16;         // index into edge-padded sequence
            if (j > 1023) j = 1023;          // edge pad
            As[k16][ml] = x[(n << 10) + j];
        }
        // B tile: wT rows kt*16..+16, cols n0..+128
#pragma unroll
        for (int it = 0; it < 2; it++) {
            int f4 = tid + it * 256;      // 0..511
            int k16 = f4 >> 5;
            int d4 = f4 & 31;
            *(float4*)&Bs[k16][d4 * 4] =
                *(const float4*)(g_wT + (size_t)(kt * 16 + k16) * DM + n0 + d4 * 4);
        }
        __syncthreads();
#pragma unroll
        for (int k = 0; k < 16; k++) mm_step(&As[k][0], &Bs[k][0], ty, tx, acc);
    }

    // epilogue: write emb (no bias, no activation)
#pragma unroll
    for (int i = 0; i < 8; i++) {
        size_t base = (size_t)(m0 + ty * 8 + i) * DM + n0 + tx * 8;
#pragma unroll
        for (int q = 0; q < 4; q++) {
            float2 v = unpack2(acc[i][q]);
            *(float2*)(g_emb + base + 2 * q) = v;
        }
    }
}

// ---------------- kernels 2/3: 768x768 GEMM with fused epilogue ----------------
template <int RELU, int ADDEMB>
__global__ void __launch_bounds__(256) k_mlp_gemm(const float* __restrict__ A,
                                                  const float* __restrict__ Bm,
                                                  const float* __restrict__ bias,
                                                  const float* __restrict__ addsrc,
                                                  float* __restrict__ C) {
    __shared__ __align__(16) float As[2][16][132];
    __shared__ __align__(16) float Bs[2][16][132];
    int tid = threadIdx.x;
    int tx = tid & 15, ty = tid >> 4;
    int m0 = blockIdx.y << 7;
    int n0 = blockIdx.x << 7;

    unsigned long long acc[8][4];
#pragma unroll
    for (int i = 0; i < 8; i++)
#pragma unroll
        for (int q = 0; q < 4; q++) acc[i][q] = 0ULL;

    float4 ra[2], rb[2];

    auto load_regs = [&](int kt) {
#pragma unroll
        for (int q = 0; q < 2; q++) {
            int f4 = tid * 2 + q;
            int row = f4 >> 2, c4 = f4 & 3;
            ra[q] = *(const float4*)(A + (size_t)(m0 + row) * 768 + kt * 16 + c4 * 4);
            int kl = f4 >> 5, d4 = f4 & 31;
            rb[q] = *(const float4*)(Bm + (size_t)(kt * 16 + kl) * 768 + n0 + d4 * 4);
        }
    };
    auto store_smem = [&](int s) {
#pragma unroll
        for (int q = 0; q < 2; q++) {
            int f4 = tid * 2 + q;
            int row = f4 >> 2, c4 = f4 & 3;
            As[s][c4 * 4 + 0][row] = ra[q].x;
            As[s][c4 * 4 + 1][row] = ra[q].y;
            As[s][c4 * 4 + 2][row] = ra[q].z;
            As[s][c4 * 4 + 3][row] = ra[q].w;
            int kl = f4 >> 5, d4 = f4 & 31;
            *(float4*)&Bs[s][kl][d4 * 4] = rb[q];
        }
    };

    load_regs(0);
    store_smem(0);
    __syncthreads();
    int s = 0;
    for (int kt = 0; kt < 48; kt++) {
        if (kt < 47) load_regs(kt + 1);
#pragma unroll
        for (int k = 0; k < 16; k++) mm_step(&As[s][k][0], &Bs[s][k][0], ty, tx, acc);
        if (kt < 47) {
            store_smem(s ^ 1);
            __syncthreads();
            s ^= 1;
        }
    }

    // epilogue
#pragma unroll
    for (int i = 0; i < 8; i++) {
        int m = m0 + ty * 8 + i;
        size_t base = (size_t)m * 768 + n0 + tx * 8;
#pragma unroll
        for (int q = 0; q < 4; q++) {
            float2 v = unpack2(acc[i][q]);
            int j = n0 + tx * 8 + 2 * q;
            v.x += bias[j];
            v.y += bias[j + 1];
            if (RELU) {
                v.x = fmaxf(v.x, 0.0f);
                v.y = fmaxf(v.y, 0.0f);
            }
            if (ADDEMB) {
                float2 e = *(const float2*)(addsrc + base + 2 * q);
                v.x += e.x;
                v.y += e.y;
            }
            *(float2*)(C + base + 2 * q) = v;
        }
    }
}

extern "C" void kernel_launch(void* const* d_in, const int* in_sizes, int n_in,
                              void* d_out, int out_size) {
    (void)in_sizes; (void)n_in; (void)out_size;
    const float* x      = (const float*)d_in[0];
    const float* conv_w = (const float*)d_in[1];
    const float* w1     = (const float*)d_in[2];
    const float* b1     = (const float*)d_in[3];
    const float* w2     = (const float*)d_in[4];
    const float* b2     = (const float*)d_in[5];
    float* out = (float*)d_out;

    float* emb_ptr;
    float* h1_ptr;
    cudaGetSymbolAddress((void**)&emb_ptr, g_emb);
    cudaGetSymbolAddress((void**)&h1_ptr, g_h1);

    k_transpose_w<<<(KCONV * DM + 255) / 256, 256>>>(conv_w);

    dim3 grid(DM / 128, MTOT / 128);  // (6, 1344)
    k_embed<<<grid, 256>>>(x);
    k_mlp_gemm<1, 0><<<grid, 256>>>(emb_ptr, w1, b1, nullptr, h1_ptr);
    k_mlp_gemm<0, 1><<<grid, 256>>>(h1_ptr, w2, b2, emb_ptr, out);
}

// round 3
// speedup vs baseline: 1.9901x; 1.9901x over previous
#include <cuda_runtime.h>
#include <cuda_bf16.h>
#include <cstdint>

#define MTOT 172032
#define DM   768
#define MT_TILES 1344
#define NT_TILES 6
#define NCH  12                 // K chunks of 64
#define TILE 18432              // 128 rows * 144 bytes
#define STG_BYTES (4*TILE)      // Ah|Al|Bh|Bl
#define SMEM_GEMM (2*STG_BYTES) // 147456
#define SMEM_EMBED STG_BYTES    // 73728

// ---------------- global scratch (bf16 hi/lo planes) ----------------
__device__ __nv_bfloat16 g_embh[(size_t)MTOT * DM];
__device__ __nv_bfloat16 g_embl[(size_t)MTOT * DM];
__device__ __nv_bfloat16 g_h1h [(size_t)MTOT * DM];
__device__ __nv_bfloat16 g_h1l [(size_t)MTOT * DM];
__device__ __nv_bfloat16 g_w1h[DM * DM], g_w1l[DM * DM];   // [n][k]
__device__ __nv_bfloat16 g_w2h[DM * DM], g_w2l[DM * DM];   // [n][k]
__device__ __nv_bfloat16 g_cwh[DM * 64], g_cwl[DM * 64];   // [n][64] padded K

// ---------------- helpers ----------------
__device__ __forceinline__ uint32_t smem_u32(const void* p) {
    uint32_t a;
    asm("{ .reg .u64 t; cvta.to.shared.u64 t, %1; cvt.u32.u64 %0, t; }" : "=r"(a) : "l"(p));
    return a;
}
__device__ __forceinline__ void cp16(uint32_t s, const void* g) {
    asm volatile("cp.async.cg.shared.global [%0], [%1], 16;" ::
                 "r"(s), "l"(__cvta_generic_to_global(g)));
}
#define CP_COMMIT() asm volatile("cp.async.commit_group;" ::: "memory")
#define CP_WAIT(n)  asm volatile("cp.async.wait_group %0;" :: "n"(n) : "memory")

__device__ __forceinline__ void ldmat4(uint32_t (&r)[4], uint32_t a) {
    asm volatile("ldmatrix.sync.aligned.m8n8.x4.shared.b16 {%0,%1,%2,%3}, [%4];"
                 : "=r"(r[0]), "=r"(r[1]), "=r"(r[2]), "=r"(r[3]) : "r"(a));
}
__device__ __forceinline__ void mma16816(float (&d)[4], const uint32_t* a, uint32_t b0, uint32_t b1) {
    asm volatile("mma.sync.aligned.m16n8k16.row.col.f32.bf16.bf16.f32 "
                 "{%0,%1,%2,%3},{%4,%5,%6,%7},{%8,%9},{%0,%1,%2,%3};"
                 : "+f"(d[0]), "+f"(d[1]), "+f"(d[2]), "+f"(d[3])
                 : "r"(a[0]), "r"(a[1]), "r"(a[2]), "r"(a[3]), "r"(b0), "r"(b1));
}
__device__ __forceinline__ void split_hl(float v, __nv_bfloat16& h, __nv_bfloat16& l) {
    h = __float2bfloat16(v);
    l = __float2bfloat16(v - __bfloat162float(h));
}

// ---- one K-chunk of 3-pass MMA: stg points at [Ah|Al|Bh|Bl] ----
__device__ __forceinline__ void compute_chunk(uint32_t stg, int wm, int wn, int lane,
                                              int nks, float (&acc)[2][8][4]) {
    uint32_t r16 = (uint32_t)(lane & 15) * 144;
    uint32_t kbase = (uint32_t)(8 * (lane >> 4)) * 2;
    for (int k16 = 0; k16 < nks; k16++) {
        uint32_t kc = kbase + (uint32_t)(k16 * 32);
        uint32_t ah[2][4], al[2][4];
#pragma unroll
        for (int mf = 0; mf < 2; mf++) {
            uint32_t ao = (uint32_t)(wm + mf * 16) * 144 + r16 + kc;
            ldmat4(ah[mf], stg + ao);
            ldmat4(al[mf], stg + TILE + ao);
        }
        uint32_t bh[4][4], bl[4][4];
#pragma unroll
        for (int ng = 0; ng < 4; ng++) {
            uint32_t bo = (uint32_t)(wn + ng * 16) * 144 + r16 + kc;
            ldmat4(bh[ng], stg + 2 * TILE + bo);
            ldmat4(bl[ng], stg + 3 * TILE + bo);
        }
#pragma unroll
        for (int mf = 0; mf < 2; mf++)
#pragma unroll
            for (int nf = 0; nf < 8; nf++) {
                int ng = nf >> 1, sub = nf & 1;
                uint32_t h0 = sub ? bh[ng][1] : bh[ng][0];
                uint32_t h1 = sub ? bh[ng][3] : bh[ng][2];
                uint32_t l0 = sub ? bl[ng][1] : bl[ng][0];
                uint32_t l1 = sub ? bl[ng][3] : bl[ng][2];
                mma16816(acc[mf][nf], ah[mf], h0, h1);
                mma16816(acc[mf][nf], ah[mf], l0, l1);
                mma16816(acc[mf][nf], al[mf], h0, h1);
            }
    }
}

// ---- stage loader: 128x64 bf16 x4 planes via cp.async ----
__device__ __forceinline__ void load_stage(uint32_t stg,
                                           const __nv_bfloat16* Ah, const __nv_bfloat16* Al,
                                           const __nv_bfloat16* Bh, const __nv_bfloat16* Bl,
                                           int m0, int n0, int k0, int tid) {
    for (int idx = tid; idx < 1024; idx += 256) {
        int row = idx >> 3, c = idx & 7;
        uint32_t so = (uint32_t)row * 144 + (uint32_t)c * 16;
        size_t ga = (size_t)(m0 + row) * DM + k0 + c * 8;
        size_t gb = (size_t)(n0 + row) * DM + k0 + c * 8;
        cp16(stg + so, Ah + ga);
        cp16(stg + TILE + so, Al + ga);
        cp16(stg + 2 * TILE + so, Bh + gb);
        cp16(stg + 3 * TILE + so, Bl + gb);
    }
}

// ---------------- prep kernels ----------------
__global__ void k_prep_w(const float* __restrict__ w, __nv_bfloat16* __restrict__ th,
                         __nv_bfloat16* __restrict__ tl) {
    int gid = blockIdx.x * 256 + threadIdx.x;
    if (gid >= DM * DM) return;
    int k = gid / DM, n = gid - k * DM;
    __nv_bfloat16 h, l;
    split_hl(w[gid], h, l);
    th[(size_t)n * DM + k] = h;
    tl[(size_t)n * DM + k] = l;
}
__global__ void k_prep_cw(const float* __restrict__ cw) {
    int gid = blockIdx.x * 256 + threadIdx.x;
    if (gid >= DM * 64) return;
    int n = gid >> 6, k = gid & 63;
    float v = 0.f;
    if (k < 48) { int i = k & 15, t = k >> 4; v = cw[n * 48 + i * 3 + t]; }
    __nv_bfloat16 h, l;
    split_hl(v, h, l);
    g_cwh[gid] = h;
    g_cwl[gid] = l;
}

// ---------------- embed: gather + K=48 MMA -> emb hi/lo ----------------
__global__ void __launch_bounds__(256, 1) k_embed(const float* __restrict__ x) {
    extern __shared__ __align__(128) char smem[];
    uint32_t sb = smem_u32(smem);
    int tid = threadIdx.x, wid = tid >> 5, lane = tid & 31;
    int wm = (wid & 3) * 32, wn = (wid >> 2) * 64;
    int m0 = blockIdx.y * 128, n0 = blockIdx.x * 128;

    // B planes via cp.async: cw [n][64]
    for (int idx = tid; idx < 1024; idx += 256) {
        int row = idx >> 3, c = idx & 7;
        uint32_t so = (uint32_t)row * 144 + (uint32_t)c * 16;
        size_t gb = (size_t)(n0 + row) * 64 + c * 8;
        cp16(sb + 2 * TILE + so, g_cwh + gb);
        cp16(sb + 3 * TILE + so, g_cwl + gb);
    }
    CP_COMMIT();
    // A gather: 128 tokens x 64 (k>=48 zero), hi/lo planes
    int seq = blockIdx.y;
    for (int e = tid; e < 8192; e += 256) {
        int r = e >> 6, k = e & 63;
        float val = 0.f;
        if (k < 48) {
            int t = k >> 4, i = k & 15;
            int pp = (r + t + 127) & 127;
            int j = pp * 8 + i;
            if (j > 1023) j = 1023;
            val = x[(size_t)seq * 1024 + j];
        }
        __nv_bfloat16 h, l;
        split_hl(val, h, l);
        uint32_t so = (uint32_t)r * 144 + (uint32_t)k * 2;
        *(__nv_bfloat16*)(smem + so) = h;
        *(__nv_bfloat16*)(smem + TILE + so) = l;
    }
    CP_WAIT(0);
    __syncthreads();

    float acc[2][8][4];
#pragma unroll
    for (int a = 0; a < 2; a++)
#pragma unroll
        for (int b = 0; b < 8; b++)
#pragma unroll
            for (int c = 0; c < 4; c++) acc[a][b][c] = 0.f;

    compute_chunk(sb, wm, wn, lane, 3, acc);

    // epilogue: write hi/lo planes
    int rin = lane >> 2, colp = (lane & 3) * 2;
#pragma unroll
    for (int mf = 0; mf < 2; mf++)
#pragma unroll
        for (int nf = 0; nf < 8; nf++) {
            int gn = n0 + wn + nf * 8 + colp;
#pragma unroll
            for (int half = 0; half < 2; half++) {
                int gm = m0 + wm + mf * 16 + rin + half * 8;
                float v0 = acc[mf][nf][half * 2], v1 = acc[mf][nf][half * 2 + 1];
                __nv_bfloat162 hp, lp;
                split_hl(v0, hp.x, lp.x);
                split_hl(v1, hp.y, lp.y);
                size_t o = (size_t)gm * DM + gn;
                *(__nv_bfloat162*)(g_embh + o) = hp;
                *(__nv_bfloat162*)(g_embl + o) = lp;
            }
        }
}

// ---------------- main GEMM: MODE0 = relu(A@W+b) -> hi/lo ; MODE1 = A@W+b+res -> fp32 ----------------
template <int MODE>
__global__ void __launch_bounds__(256, 1) k_gemm(const __nv_bfloat16* __restrict__ Ah,
                                                 const __nv_bfloat16* __restrict__ Al,
                                                 const __nv_bfloat16* __restrict__ Bh,
                                                 const __nv_bfloat16* __restrict__ Bl,
                                                 const float* __restrict__ bias,
                                                 __nv_bfloat16* __restrict__ Oh,
                                                 __nv_bfloat16* __restrict__ Ol,
                                                 float* __restrict__ outF) {
    extern __shared__ __align__(128) char smem[];
    uint32_t sb = smem_u32(smem);
    int tid = threadIdx.x, wid = tid >> 5, lane = tid & 31;
    int wm = (wid & 3) * 32, wn = (wid >> 2) * 64;
    int m0 = blockIdx.y * 128, n0 = blockIdx.x * 128;

    float acc[2][8][4];
#pragma unroll
    for (int a = 0; a < 2; a++)
#pragma unroll
        for (int b = 0; b < 8; b++)
#pragma unroll
            for (int c = 0; c < 4; c++) acc[a][b][c] = 0.f;

    load_stage(sb, Ah, Al, Bh, Bl, m0, n0, 0, tid);
    CP_COMMIT();
    load_stage(sb + STG_BYTES, Ah, Al, Bh, Bl, m0, n0, 64, tid);
    CP_COMMIT();

    for (int c = 0; c < NCH; c++) {
        if (c == NCH - 1) { CP_WAIT(0); } else { CP_WAIT(1); }
        __syncthreads();
        uint32_t stg = sb + (uint32_t)(c & 1) * STG_BYTES;
        compute_chunk(stg, wm, wn, lane, 4, acc);
        __syncthreads();
        if (c + 2 < NCH) {
            load_stage(stg, Ah, Al, Bh, Bl, m0, n0, (c + 2) * 64, tid);
            CP_COMMIT();
        }
    }

    // epilogue
    int rin = lane >> 2, colp = (lane & 3) * 2;
#pragma unroll
    for (int mf = 0; mf < 2; mf++)
#pragma unroll
        for (int nf = 0; nf < 8; nf++) {
            int gn = n0 + wn + nf * 8 + colp;
            float b0 = bias[gn], b1 = bias[gn + 1];
#pragma unroll
            for (int half = 0; half < 2; half++) {
                int gm = m0 + wm + mf * 16 + rin + half * 8;
                size_t o = (size_t)gm * DM + gn;
                float v0 = acc[mf][nf][half * 2] + b0;
                float v1 = acc[mf][nf][half * 2 + 1] + b1;
                if (MODE == 0) {
                    v0 = fmaxf(v0, 0.f);
                    v1 = fmaxf(v1, 0.f);
                    __nv_bfloat162 hp, lp;
                    split_hl(v0, hp.x, lp.x);
                    split_hl(v1, hp.y, lp.y);
                    *(__nv_bfloat162*)(Oh + o) = hp;
                    *(__nv_bfloat162*)(Ol + o) = lp;
                } else {
                    __nv_bfloat162 rh = *(const __nv_bfloat162*)(g_embh + o);
                    __nv_bfloat162 rl = *(const __nv_bfloat162*)(g_embl + o);
                    float2 r;
                    r.x = v0 + __bfloat162float(rh.x) + __bfloat162float(rl.x);
                    r.y = v1 + __bfloat162float(rh.y) + __bfloat162float(rl.y);
                    *(float2*)(outF + o) = r;
                }
            }
        }
}

// ---------------- launcher ----------------
extern "C" void kernel_launch(void* const* d_in, const int* in_sizes, int n_in,
                              void* d_out, int out_size) {
    (void)in_sizes; (void)n_in; (void)out_size;
    const float* x      = (const float*)d_in[0];
    const float* conv_w = (const float*)d_in[1];
    const float* w1     = (const float*)d_in[2];
    const float* b1     = (const float*)d_in[3];
    const float* w2     = (const float*)d_in[4];
    const float* b2     = (const float*)d_in[5];
    float* out = (float*)d_out;

    __nv_bfloat16 *embh, *embl, *h1h, *h1l, *w1h, *w1l, *w2h, *w2l;
    cudaGetSymbolAddress((void**)&embh, g_embh);
    cudaGetSymbolAddress((void**)&embl, g_embl);
    cudaGetSymbolAddress((void**)&h1h, g_h1h);
    cudaGetSymbolAddress((void**)&h1l, g_h1l);
    cudaGetSymbolAddress((void**)&w1h, g_w1h);
    cudaGetSymbolAddress((void**)&w1l, g_w1l);
    cudaGetSymbolAddress((void**)&w2h, g_w2h);
    cudaGetSymbolAddress((void**)&w2l, g_w2l);

    cudaFuncSetAttribute(k_embed, cudaFuncAttributeMaxDynamicSharedMemorySize, SMEM_EMBED);
    cudaFuncSetAttribute(k_gemm<0>, cudaFuncAttributeMaxDynamicSharedMemorySize, SMEM_GEMM);
    cudaFuncSetAttribute(k_gemm<1>, cudaFuncAttributeMaxDynamicSharedMemorySize, SMEM_GEMM);

    k_prep_w<<<(DM * DM + 255) / 256, 256>>>(w1, w1h, w1l);
    k_prep_w<<<(DM * DM + 255) / 256, 256>>>(w2, w2h, w2l);
    k_prep_cw<<<(DM * 64 + 255) / 256, 256>>>(conv_w);

    dim3 grid(NT_TILES, MT_TILES);
    k_embed<<<grid, 256, SMEM_EMBED>>>(x);
    k_gemm<0><<<grid, 256, SMEM_GEMM>>>(embh, embl, w1h, w1l, b1, h1h, h1l, nullptr);
    k_gemm<1><<<grid, 256, SMEM_GEMM>>>(h1h, h1l, w2h, w2l, b2, nullptr, nullptr, out);
}

// round 4
// speedup vs baseline: 2.3554x; 1.1835x over previous
#include <cuda_runtime.h>
#include <cuda_bf16.h>
#include <cstdint>

#define MTOT 172032
#define DM   768
#define MT_TILES 1344
#define NT_TILES 6

#define PITCH 80                 // bytes per 32-bf16 row (conflict-free)
#define PLANE (128 * PITCH)      // 10240
#define STG   (4 * PLANE)        // 40960: Ah|Al|Bh|Bl
#define SMEM_GEMM (2 * STG)      // 81920 -> 2 CTAs/SM

// ---------------- global scratch (bf16 hi/lo planes, row-major [m][K]) ----------------
__device__ __nv_bfloat16 g_xh [(size_t)MTOT * 64];
__device__ __nv_bfloat16 g_xl [(size_t)MTOT * 64];
__device__ __nv_bfloat16 g_embh[(size_t)MTOT * DM];
__device__ __nv_bfloat16 g_embl[(size_t)MTOT * DM];
__device__ __nv_bfloat16 g_h1h [(size_t)MTOT * DM];
__device__ __nv_bfloat16 g_h1l [(size_t)MTOT * DM];
__device__ __nv_bfloat16 g_w1h[DM * DM], g_w1l[DM * DM];   // [n][k]
__device__ __nv_bfloat16 g_w2h[DM * DM], g_w2l[DM * DM];   // [n][k]
__device__ __nv_bfloat16 g_cwh[DM * 64], g_cwl[DM * 64];   // [n][64]

// ---------------- helpers ----------------
__device__ __forceinline__ uint32_t smem_u32(const void* p) {
    uint32_t a;
    asm("{ .reg .u64 t; cvta.to.shared.u64 t, %1; cvt.u32.u64 %0, t; }" : "=r"(a) : "l"(p));
    return a;
}
__device__ __forceinline__ void cp16(uint32_t s, const void* g) {
    asm volatile("cp.async.cg.shared.global [%0], [%1], 16;" ::
                 "r"(s), "l"(__cvta_generic_to_global(g)));
}
#define CP_COMMIT() asm volatile("cp.async.commit_group;" ::: "memory")
#define CP_WAIT0()  asm volatile("cp.async.wait_group 0;" ::: "memory")
#define CP_WAIT1()  asm volatile("cp.async.wait_group 1;" ::: "memory")

__device__ __forceinline__ void ldmat4(uint32_t (&r)[4], uint32_t a) {
    asm volatile("ldmatrix.sync.aligned.m8n8.x4.shared.b16 {%0,%1,%2,%3}, [%4];"
                 : "=r"(r[0]), "=r"(r[1]), "=r"(r[2]), "=r"(r[3]) : "r"(a));
}
__device__ __forceinline__ void mma16816(float (&d)[4], const uint32_t* a, uint32_t b0, uint32_t b1) {
    asm volatile("mma.sync.aligned.m16n8k16.row.col.f32.bf16.bf16.f32 "
                 "{%0,%1,%2,%3},{%4,%5,%6,%7},{%8,%9},{%0,%1,%2,%3};"
                 : "+f"(d[0]), "+f"(d[1]), "+f"(d[2]), "+f"(d[3])
                 : "r"(a[0]), "r"(a[1]), "r"(a[2]), "r"(a[3]), "r"(b0), "r"(b1));
}
__device__ __forceinline__ void split_hl(float v, __nv_bfloat16& h, __nv_bfloat16& l) {
    h = __float2bfloat16(v);
    l = __float2bfloat16(v - __bfloat162float(h));
}

// ---- one BK=32 chunk of 3-pass MMA ----
__device__ __forceinline__ void compute_chunk(uint32_t stg, int wm, int wn, int lane,
                                              float (&acc)[2][8][4]) {
    uint32_t r16 = (uint32_t)(lane & 15) * PITCH;
    uint32_t khalf = (uint32_t)(lane >> 4) * 16;
#pragma unroll
    for (int k16 = 0; k16 < 2; k16++) {
        uint32_t kc = khalf + (uint32_t)(k16 * 32);
        uint32_t ah[2][4], al[2][4];
#pragma unroll
        for (int mf = 0; mf < 2; mf++) {
            uint32_t ao = (uint32_t)(wm + mf * 16) * PITCH + r16 + kc;
            ldmat4(ah[mf], stg + ao);
            ldmat4(al[mf], stg + PLANE + ao);
        }
#pragma unroll
        for (int ng = 0; ng < 4; ng++) {
            uint32_t bo = (uint32_t)(wn + ng * 16) * PITCH + r16 + kc;
            uint32_t bh[4], bl[4];
            ldmat4(bh, stg + 2 * PLANE + bo);
            ldmat4(bl, stg + 3 * PLANE + bo);
#pragma unroll
            for (int mf = 0; mf < 2; mf++)
#pragma unroll
                for (int sub = 0; sub < 2; sub++) {
                    int nf = ng * 2 + sub;
                    uint32_t h0 = sub ? bh[1] : bh[0];
                    uint32_t h1 = sub ? bh[3] : bh[2];
                    uint32_t l0 = sub ? bl[1] : bl[0];
                    uint32_t l1 = sub ? bl[3] : bl[2];
                    mma16816(acc[mf][nf], ah[mf], h0, h1);
                    mma16816(acc[mf][nf], ah[mf], l0, l1);
                    mma16816(acc[mf][nf], al[mf], h0, h1);
                }
        }
    }
}

// ---- stage loader: 4 planes of 128x32 bf16 ----
template <int KD>
__device__ __forceinline__ void load_stage(uint32_t stg,
                                           const __nv_bfloat16* __restrict__ Ah,
                                           const __nv_bfloat16* __restrict__ Al,
                                           const __nv_bfloat16* __restrict__ Bh,
                                           const __nv_bfloat16* __restrict__ Bl,
                                           int m0, int n0, int k0, int tid) {
#pragma unroll
    for (int it = 0; it < 2; it++) {
        int idx = tid + it * 256;                  // 0..511
        int row = idx >> 2, c = idx & 3;
        uint32_t so = (uint32_t)row * PITCH + (uint32_t)c * 16;
        size_t ga = (size_t)(m0 + row) * KD + k0 + c * 8;
        size_t gb = (size_t)(n0 + row) * KD + k0 + c * 8;
        cp16(stg + so, Ah + ga);
        cp16(stg + PLANE + so, Al + ga);
        cp16(stg + 2 * PLANE + so, Bh + gb);
        cp16(stg + 3 * PLANE + so, Bl + gb);
    }
}

// ---------------- prep kernels ----------------
__global__ void k_prep_w(const float* __restrict__ w, __nv_bfloat16* __restrict__ th,
                         __nv_bfloat16* __restrict__ tl) {
    int gid = blockIdx.x * 256 + threadIdx.x;
    if (gid >= DM * DM) return;
    int k = gid / DM, n = gid - k * DM;
    __nv_bfloat16 h, l;
    split_hl(w[gid], h, l);
    th[(size_t)n * DM + k] = h;
    tl[(size_t)n * DM + k] = l;
}
__global__ void k_prep_cw(const float* __restrict__ cw) {
    int gid = blockIdx.x * 256 + threadIdx.x;
    if (gid >= DM * 64) return;
    int n = gid >> 6, k = gid & 63;
    float v = 0.f;
    if (k < 48) { int i = k & 15, t = k >> 4; v = cw[n * 48 + i * 3 + t]; }
    __nv_bfloat16 h, l;
    split_hl(v, h, l);
    g_cwh[gid] = h;
    g_cwl[gid] = l;
}
// gather x -> A planes [m][64] (zero-padded K 48..63), coalesced writes
__global__ void k_prep_x(const float* __restrict__ x) {
    int gid = blockIdx.x * 256 + threadIdx.x;
    if (gid >= MTOT * 64) return;
    int m = gid >> 6, k = gid & 63;
    int seq = m >> 7, r = m & 127;
    float v = 0.f;
    if (k < 48) {
        int t = k >> 4, i = k & 15;
        int pp = (r + t + 127) & 127;
        int j = pp * 8 + i;
        if (j > 1023) j = 1023;
        v = x[(size_t)seq * 1024 + j];
    }
    __nv_bfloat16 h, l;
    split_hl(v, h, l);
    g_xh[gid] = h;
    g_xl[gid] = l;
}

// ---------------- unified GEMM ----------------
// MODE 0: relu(A@B + bias) -> hi/lo planes
// MODE 1: A@B + bias + (embh+embl) -> fp32 out
// MODE 2: A@B -> hi/lo planes (embed)
template <int MODE, int KD>
__global__ void __launch_bounds__(256, 2) k_gemm(const __nv_bfloat16* __restrict__ Ah,
                                                 const __nv_bfloat16* __restrict__ Al,
                                                 const __nv_bfloat16* __restrict__ Bh,
                                                 const __nv_bfloat16* __restrict__ Bl,
                                                 const float* __restrict__ bias,
                                                 __nv_bfloat16* __restrict__ Oh,
                                                 __nv_bfloat16* __restrict__ Ol,
                                                 float* __restrict__ outF) {
    constexpr int NCH = KD / 32;
    extern __shared__ __align__(128) char smem[];
    uint32_t sb = smem_u32(smem);
    int tid = threadIdx.x, wid = tid >> 5, lane = tid & 31;
    int wm = (wid & 3) * 32, wn = (wid >> 2) * 64;
    int m0 = blockIdx.y * 128, n0 = blockIdx.x * 128;

    float acc[2][8][4];
#pragma unroll
    for (int a = 0; a < 2; a++)
#pragma unroll
        for (int b = 0; b < 8; b++)
#pragma unroll
            for (int c = 0; c < 4; c++) acc[a][b][c] = 0.f;

    load_stage<KD>(sb, Ah, Al, Bh, Bl, m0, n0, 0, tid);
    CP_COMMIT();
    load_stage<KD>(sb + STG, Ah, Al, Bh, Bl, m0, n0, 32, tid);
    CP_COMMIT();

#pragma unroll 1
    for (int c = 0; c < NCH; c++) {
        if (c == NCH - 1) { CP_WAIT0(); } else { CP_WAIT1(); }
        __syncthreads();
        uint32_t stg = sb + (uint32_t)(c & 1) * STG;
        compute_chunk(stg, wm, wn, lane, acc);
        __syncthreads();
        if (c + 2 < NCH) {
            load_stage<KD>(stg, Ah, Al, Bh, Bl, m0, n0, (c + 2) * 32, tid);
            CP_COMMIT();
        }
    }

    // ---- smem-staged epilogue ----
    int rin = lane >> 2, colp = (lane & 3) * 2;
    if (MODE == 1) {
        float* smf = (float*)smem;                 // pitch 132 floats (528B)
#pragma unroll
        for (int mf = 0; mf < 2; mf++)
#pragma unroll
            for (int nf = 0; nf < 8; nf++) {
                int cn = wn + nf * 8 + colp;
                float b0 = bias[n0 + cn], b1 = bias[n0 + cn + 1];
#pragma unroll
                for (int half = 0; half < 2; half++) {
                    int rr = wm + mf * 16 + rin + half * 8;
                    float2 v;
                    v.x = acc[mf][nf][half * 2] + b0;
                    v.y = acc[mf][nf][half * 2 + 1] + b1;
                    *(float2*)(smf + (size_t)rr * 132 + cn) = v;
                }
            }
        __syncthreads();
        for (int i = tid; i < 8192; i += 256) {
            int r = i >> 6, c = i & 63;
            float2 v = *(float2*)(smf + (size_t)r * 132 + c * 2);
            size_t o = (size_t)(m0 + r) * DM + n0 + c * 2;
            __nv_bfloat162 rh = *(const __nv_bfloat162*)(g_embh + o);
            __nv_bfloat162 rl = *(const __nv_bfloat162*)(g_embl + o);
            v.x += __bfloat162float(rh.x) + __bfloat162float(rl.x);
            v.y += __bfloat162float(rh.y) + __bfloat162float(rl.y);
            *(float2*)(outF + o) = v;
        }
    } else {
        // bf16 hi/lo staging: two planes, pitch 272B
        char* smc = smem;
#pragma unroll
        for (int mf = 0; mf < 2; mf++)
#pragma unroll
            for (int nf = 0; nf < 8; nf++) {
                int cn = wn + nf * 8 + colp;
                float b0 = (MODE == 0) ? bias[n0 + cn] : 0.f;
                float b1 = (MODE == 0) ? bias[n0 + cn + 1] : 0.f;
#pragma unroll
                for (int half = 0; half < 2; half++) {
                    int rr = wm + mf * 16 + rin + half * 8;
                    float v0 = acc[mf][nf][half * 2] + b0;
                    float v1 = acc[mf][nf][half * 2 + 1] + b1;
                    if (MODE == 0) { v0 = fmaxf(v0, 0.f); v1 = fmaxf(v1, 0.f); }
                    __nv_bfloat162 hp, lp;
                    split_hl(v0, hp.x, lp.x);
                    split_hl(v1, hp.y, lp.y);
                    *(__nv_bfloat162*)(smc + (size_t)rr * 272 + cn * 2) = hp;
                    *(__nv_bfloat162*)(smc + 34816 + (size_t)rr * 272 + cn * 2) = lp;
                }
            }
        __syncthreads();
        for (int i = tid; i < 2048; i += 256) {
            int r = i >> 4, c = i & 15;
            uint4 vh = *(uint4*)(smc + (size_t)r * 272 + c * 16);
            uint4 vl = *(uint4*)(smc + 34816 + (size_t)r * 272 + c * 16);
            size_t o = (size_t)(m0 + r) * DM + n0 + c * 8;
            *(uint4*)(Oh + o) = vh;
            *(uint4*)(Ol + o) = vl;
        }
    }
}

// ---------------- launcher ----------------
extern "C" void kernel_launch(void* const* d_in, const int* in_sizes, int n_in,
                              void* d_out, int out_size) {
    (void)in_sizes; (void)n_in; (void)out_size;
    const float* x      = (const float*)d_in[0];
    const float* conv_w = (const float*)d_in[1];
    const float* w1     = (const float*)d_in[2];
    const float* b1     = (const float*)d_in[3];
    const float* w2     = (const float*)d_in[4];
    const float* b2     = (const float*)d_in[5];
    float* out = (float*)d_out;

    __nv_bfloat16 *xh, *xl, *embh, *embl, *h1h, *h1l, *w1h, *w1l, *w2h, *w2l, *cwh, *cwl;
    cudaGetSymbolAddress((void**)&xh, g_xh);
    cudaGetSymbolAddress((void**)&xl, g_xl);
    cudaGetSymbolAddress((void**)&embh, g_embh);
    cudaGetSymbolAddress((void**)&embl, g_embl);
    cudaGetSymbolAddress((void**)&h1h, g_h1h);
    cudaGetSymbolAddress((void**)&h1l, g_h1l);
    cudaGetSymbolAddress((void**)&w1h, g_w1h);
    cudaGetSymbolAddress((void**)&w1l, g_w1l);
    cudaGetSymbolAddress((void**)&w2h, g_w2h);
    cudaGetSymbolAddress((void**)&w2l, g_w2l);
    cudaGetSymbolAddress((void**)&cwh, g_cwh);
    cudaGetSymbolAddress((void**)&cwl, g_cwl);

    cudaFuncSetAttribute((const void*)k_gemm<0, 768>, cudaFuncAttributeMaxDynamicSharedMemorySize, SMEM_GEMM);
    cudaFuncSetAttribute((const void*)k_gemm<1, 768>, cudaFuncAttributeMaxDynamicSharedMemorySize, SMEM_GEMM);
    cudaFuncSetAttribute((const void*)k_gemm<2, 64>,  cudaFuncAttributeMaxDynamicSharedMemorySize, SMEM_GEMM);

    k_prep_w<<<(DM * DM + 255) / 256, 256>>>(w1, w1h, w1l);
    k_prep_w<<<(DM * DM + 255) / 256, 256>>>(w2, w2h, w2l);
    k_prep_cw<<<(DM * 64 + 255) / 256, 256>>>(conv_w);
    k_prep_x<<<(MTOT * 64 + 255) / 256, 256>>>(x);

    dim3 grid(NT_TILES, MT_TILES);
    k_gemm<2, 64><<<grid, 256, SMEM_GEMM>>>(xh, xl, cwh, cwl, nullptr, embh, embl, nullptr);
    k_gemm<0, 768><<<grid, 256, SMEM_GEMM>>>(embh, embl, w1h, w1l, b1, h1h, h1l, nullptr);
    k_gemm<1, 768><<<grid, 256, SMEM_GEMM>>>(h1h, h1l, w2h, w2l, b2, nullptr, nullptr, out);
}

// round 5
// speedup vs baseline: 3.1959x; 1.3569x over previous
#include <cuda_runtime.h>
#include <cuda_fp16.h>
#include <cstdint>

#define MTOT 172032
#define DM   768
#define MT_TILES 1344
#define NT_TILES 6

#define PITCH 80                 // bytes per 32-fp16 row (conflict-free ldmatrix)
#define PLANE (128 * PITCH)      // 10240
#define STGB  (3 * PLANE)        // 30720: Ah|Al|B
#define NSTAGE 3
#define SMEM_GEMM (NSTAGE * STGB) // 92160 -> 2 CTAs/SM (180KB)

// ---------------- global scratch (fp16, row-major [m][K]) ----------------
__device__ __half g_xh [(size_t)MTOT * 64];
__device__ __half g_xl [(size_t)MTOT * 64];
__device__ __half g_embh[(size_t)MTOT * DM];
__device__ __half g_embl[(size_t)MTOT * DM];
__device__ __half g_h1h [(size_t)MTOT * DM];
__device__ __half g_h1l [(size_t)MTOT * DM];
__device__ __half g_w1[DM * DM];          // [n][k]
__device__ __half g_w2[DM * DM];          // [n][k]
__device__ __half g_cw[DM * 64];          // [n][64]

// ---------------- helpers ----------------
__device__ __forceinline__ uint32_t smem_u32(const void* p) {
    uint32_t a;
    asm("{ .reg .u64 t; cvta.to.shared.u64 t, %1; cvt.u32.u64 %0, t; }" : "=r"(a) : "l"(p));
    return a;
}
__device__ __forceinline__ void cp16(uint32_t s, const void* g) {
    asm volatile("cp.async.cg.shared.global [%0], [%1], 16;" ::
                 "r"(s), "l"(__cvta_generic_to_global(g)));
}
#define CP_COMMIT() asm volatile("cp.async.commit_group;" ::: "memory")
#define CP_WAIT2()  asm volatile("cp.async.wait_group 2;" ::: "memory")

__device__ __forceinline__ void ldmat4(uint32_t (&r)[4], uint32_t a) {
    asm volatile("ldmatrix.sync.aligned.m8n8.x4.shared.b16 {%0,%1,%2,%3}, [%4];"
                 : "=r"(r[0]), "=r"(r[1]), "=r"(r[2]), "=r"(r[3]) : "r"(a));
}
__device__ __forceinline__ void mma16816(float (&d)[4], const uint32_t* a, uint32_t b0, uint32_t b1) {
    asm volatile("mma.sync.aligned.m16n8k16.row.col.f32.f16.f16.f32 "
                 "{%0,%1,%2,%3},{%4,%5,%6,%7},{%8,%9},{%0,%1,%2,%3};"
                 : "+f"(d[0]), "+f"(d[1]), "+f"(d[2]), "+f"(d[3])
                 : "r"(a[0]), "r"(a[1]), "r"(a[2]), "r"(a[3]), "r"(b0), "r"(b1));
}
__device__ __forceinline__ void split_hl(float v, __half& h, __half& l) {
    h = __float2half(v);
    l = __float2half(v - __half2float(h));
}

// ---- one BK=32 chunk, 2-pass (Ah,Al) x B ----
__device__ __forceinline__ void compute_chunk(uint32_t stg, int wm, int wn, int lane,
                                              float (&acc)[2][8][4]) {
    uint32_t r16 = (uint32_t)(lane & 15) * PITCH;
    uint32_t khalf = (uint32_t)(lane >> 4) * 16;
#pragma unroll
    for (int k16 = 0; k16 < 2; k16++) {
        uint32_t kc = khalf + (uint32_t)(k16 * 32);
        uint32_t ah[2][4], al[2][4];
#pragma unroll
        for (int mf = 0; mf < 2; mf++) {
            uint32_t ao = (uint32_t)(wm + mf * 16) * PITCH + r16 + kc;
            ldmat4(ah[mf], stg + ao);
            ldmat4(al[mf], stg + PLANE + ao);
        }
#pragma unroll
        for (int ng = 0; ng < 4; ng++) {
            uint32_t bo = (uint32_t)(wn + ng * 16) * PITCH + r16 + kc;
            uint32_t bf[4];
            ldmat4(bf, stg + 2 * PLANE + bo);
#pragma unroll
            for (int mf = 0; mf < 2; mf++)
#pragma unroll
                for (int sub = 0; sub < 2; sub++) {
                    int nf = ng * 2 + sub;
                    uint32_t b0 = sub ? bf[1] : bf[0];
                    uint32_t b1 = sub ? bf[3] : bf[2];
                    mma16816(acc[mf][nf], ah[mf], b0, b1);
                    mma16816(acc[mf][nf], al[mf], b0, b1);
                }
        }
    }
}

// ---- stage loader: 3 planes of 128x32 fp16 ----
template <int KD>
__device__ __forceinline__ void load_stage(uint32_t stg,
                                           const __half* __restrict__ Ah,
                                           const __half* __restrict__ Al,
                                           const __half* __restrict__ Bp,
                                           int m0, int n0, int k0, int tid) {
#pragma unroll
    for (int it = 0; it < 2; it++) {
        int idx = tid + it * 256;                  // 0..511
        int row = idx >> 2, c = idx & 3;
        uint32_t so = (uint32_t)row * PITCH + (uint32_t)c * 16;
        size_t ga = (size_t)(m0 + row) * KD + k0 + c * 8;
        size_t gb = (size_t)(n0 + row) * KD + k0 + c * 8;
        cp16(stg + so, Ah + ga);
        cp16(stg + PLANE + so, Al + ga);
        cp16(stg + 2 * PLANE + so, Bp + gb);
    }
}

// ---------------- prep kernels ----------------
__global__ void k_prep_w(const float* __restrict__ w, __half* __restrict__ t) {
    int gid = blockIdx.x * 256 + threadIdx.x;
    if (gid >= DM * DM) return;
    int k = gid / DM, n = gid - k * DM;
    t[(size_t)n * DM + k] = __float2half(w[gid]);
}
__global__ void k_prep_cw(const float* __restrict__ cw) {
    int gid = blockIdx.x * 256 + threadIdx.x;
    if (gid >= DM * 64) return;
    int n = gid >> 6, k = gid & 63;
    float v = 0.f;
    if (k < 48) { int i = k & 15, t = k >> 4; v = cw[n * 48 + i * 3 + t]; }
    g_cw[gid] = __float2half(v);
}
__global__ void k_prep_x(const float* __restrict__ x) {
    int gid = blockIdx.x * 256 + threadIdx.x;
    if (gid >= MTOT * 64) return;
    int m = gid >> 6, k = gid & 63;
    int seq = m >> 7, r = m & 127;
    float v = 0.f;
    if (k < 48) {
        int t = k >> 4, i = k & 15;
        int pp = (r + t + 127) & 127;
        int j = pp * 8 + i;
        if (j > 1023) j = 1023;
        v = x[(size_t)seq * 1024 + j];
    }
    __half h, l;
    split_hl(v, h, l);
    g_xh[gid] = h;
    g_xl[gid] = l;
}

// ---------------- unified GEMM ----------------
// MODE 0: relu(A@B + bias) -> hi/lo fp16 planes
// MODE 1: A@B + bias + (embh+embl) -> fp32 out
// MODE 2: A@B -> hi/lo fp16 planes (embed)
template <int MODE, int KD>
__global__ void __launch_bounds__(256, 2) k_gemm(const __half* __restrict__ Ah,
                                                 const __half* __restrict__ Al,
                                                 const __half* __restrict__ Bp,
                                                 const float* __restrict__ bias,
                                                 __half* __restrict__ Oh,
                                                 __half* __restrict__ Ol,
                                                 float* __restrict__ outF) {
    constexpr int NCH = KD / 32;
    extern __shared__ __align__(128) char smem[];
    uint32_t sb = smem_u32(smem);
    int tid = threadIdx.x, wid = tid >> 5, lane = tid & 31;
    int wm = (wid & 3) * 32, wn = (wid >> 2) * 64;
    int m0 = blockIdx.y * 128, n0 = blockIdx.x * 128;

    float acc[2][8][4];
#pragma unroll
    for (int a = 0; a < 2; a++)
#pragma unroll
        for (int b = 0; b < 8; b++)
#pragma unroll
            for (int c = 0; c < 4; c++) acc[a][b][c] = 0.f;

#pragma unroll
    for (int s = 0; s < NSTAGE; s++) {
        if (s < NCH) load_stage<KD>(sb + (uint32_t)s * STGB, Ah, Al, Bp, m0, n0, s * 32, tid);
        CP_COMMIT();
    }

#pragma unroll 1
    for (int c = 0; c < NCH; c++) {
        CP_WAIT2();
        __syncthreads();
        uint32_t stg = sb + (uint32_t)(c % NSTAGE) * STGB;
        compute_chunk(stg, wm, wn, lane, acc);
        __syncthreads();
        if (c + NSTAGE < NCH)
            load_stage<KD>(stg, Ah, Al, Bp, m0, n0, (c + NSTAGE) * 32, tid);
        CP_COMMIT();
    }

    // ---- smem-staged epilogue ----
    int rin = lane >> 2, colp = (lane & 3) * 2;
    if (MODE == 1) {
        float* smf = (float*)smem;                 // pitch 132 floats
#pragma unroll
        for (int mf = 0; mf < 2; mf++)
#pragma unroll
            for (int nf = 0; nf < 8; nf++) {
                int cn = wn + nf * 8 + colp;
                float b0 = bias[n0 + cn], b1 = bias[n0 + cn + 1];
#pragma unroll
                for (int half = 0; half < 2; half++) {
                    int rr = wm + mf * 16 + rin + half * 8;
                    float2 v;
                    v.x = acc[mf][nf][half * 2] + b0;
                    v.y = acc[mf][nf][half * 2 + 1] + b1;
                    *(float2*)(smf + (size_t)rr * 132 + cn) = v;
                }
            }
        __syncthreads();
        for (int i = tid; i < 8192; i += 256) {
            int r = i >> 6, c = i & 63;
            float2 v = *(float2*)(smf + (size_t)r * 132 + c * 2);
            size_t o = (size_t)(m0 + r) * DM + n0 + c * 2;
            __half2 rh = *(const __half2*)(g_embh + o);
            __half2 rl = *(const __half2*)(g_embl + o);
            float2 fh = __half22float2(rh);
            float2 fl = __half22float2(rl);
            v.x += fh.x + fl.x;
            v.y += fh.y + fl.y;
            *(float2*)(outF + o) = v;
        }
    } else {
        char* smc = smem;                          // two fp16 planes, pitch 272B
#pragma unroll
        for (int mf = 0; mf < 2; mf++)
#pragma unroll
            for (int nf = 0; nf < 8; nf++) {
                int cn = wn + nf * 8 + colp;
                float b0 = (MODE == 0) ? bias[n0 + cn] : 0.f;
                float b1 = (MODE == 0) ? bias[n0 + cn + 1] : 0.f;
#pragma unroll
                for (int half = 0; half < 2; half++) {
                    int rr = wm + mf * 16 + rin + half * 8;
                    float v0 = acc[mf][nf][half * 2] + b0;
                    float v1 = acc[mf][nf][half * 2 + 1] + b1;
                    if (MODE == 0) { v0 = fmaxf(v0, 0.f); v1 = fmaxf(v1, 0.f); }
                    __half2 hp, lp;
                    split_hl(v0, hp.x, lp.x);
                    split_hl(v1, hp.y, lp.y);
                    *(__half2*)(smc + (size_t)rr * 272 + cn * 2) = hp;
                    *(__half2*)(smc + 34816 + (size_t)rr * 272 + cn * 2) = lp;
                }
            }
        __syncthreads();
        for (int i = tid; i < 2048; i += 256) {
            int r = i >> 4, c = i & 15;
            uint4 vh = *(uint4*)(smc + (size_t)r * 272 + c * 16);
            uint4 vl = *(uint4*)(smc + 34816 + (size_t)r * 272 + c * 16);
            size_t o = (size_t)(m0 + r) * DM + n0 + c * 8;
            *(uint4*)(Oh + o) = vh;
            *(uint4*)(Ol + o) = vl;
        }
    }
}

// ---------------- launcher ----------------
extern "C" void kernel_launch(void* const* d_in, const int* in_sizes, int n_in,
                              void* d_out, int out_size) {
    (void)in_sizes; (void)n_in; (void)out_size;
    const float* x      = (const float*)d_in[0];
    const float* conv_w = (const float*)d_in[1];
    const float* w1     = (const float*)d_in[2];
    const float* b1     = (const float*)d_in[3];
    const float* w2     = (const float*)d_in[4];
    const float* b2     = (const float*)d_in[5];
    float* out = (float*)d_out;

    __half *xh, *xl, *embh, *embl, *h1h, *h1l, *w1p, *w2p, *cwp;
    cudaGetSymbolAddress((void**)&xh, g_xh);
    cudaGetSymbolAddress((void**)&xl, g_xl);
    cudaGetSymbolAddress((void**)&embh, g_embh);
    cudaGetSymbolAddress((void**)&embl, g_embl);
    cudaGetSymbolAddress((void**)&h1h, g_h1h);
    cudaGetSymbolAddress((void**)&h1l, g_h1l);
    cudaGetSymbolAddress((void**)&w1p, g_w1);
    cudaGetSymbolAddress((void**)&w2p, g_w2);
    cudaGetSymbolAddress((void**)&cwp, g_cw);

    cudaFuncSetAttribute((const void*)k_gemm<0, 768>, cudaFuncAttributeMaxDynamicSharedMemorySize, SMEM_GEMM);
    cudaFuncSetAttribute((const void*)k_gemm<1, 768>, cudaFuncAttributeMaxDynamicSharedMemorySize, SMEM_GEMM);
    cudaFuncSetAttribute((const void*)k_gemm<2, 64>,  cudaFuncAttributeMaxDynamicSharedMemorySize, SMEM_GEMM);

    k_prep_w<<<(DM * DM + 255) / 256, 256>>>(w1, w1p);
    k_prep_w<<<(DM * DM + 255) / 256, 256>>>(w2, w2p);
    k_prep_cw<<<(DM * 64 + 255) / 256, 256>>>(conv_w);
    k_prep_x<<<(MTOT * 64 + 255) / 256, 256>>>(x);

    dim3 grid(NT_TILES, MT_TILES);
    k_gemm<2, 64><<<grid, 256, SMEM_GEMM>>>(xh, xl, cwp, nullptr, embh, embl, nullptr);
    k_gemm<0, 768><<<grid, 256, SMEM_GEMM>>>(embh, embl, w1p, b1, h1h, h1l, nullptr);
    k_gemm<1, 768><<<grid, 256, SMEM_GEMM>>>(h1h, h1l, w2p, b2, nullptr, nullptr, out);
}

// round 6
// speedup vs baseline: 3.8107x; 1.1924x over previous
#include <cuda_runtime.h>
#include <cuda_fp16.h>
#include <cstdint>

#define MTOT 172032
#define DM   768
#define MT_TILES 1344
#define NT_TILES 6

#define PITCH 80                 // bytes per 32-fp16 row (conflict-free ldmatrix)
#define PLANE (128 * PITCH)      // 10240

// 2-pass kernels: 3 planes/stage, 3 stages
#define STGB2  (3 * PLANE)       // 30720
#define NST2   3
#define SMEM_G2 (NST2 * STGB2)   // 92160
// 1-pass kernel: 2 planes/stage, 4 stages
#define STGB1  (2 * PLANE)       // 20480
#define NST1   4
#define SMEM_G1 (NST1 * STGB1)   // 81920 (also covers 67584B fp32 epilogue)

// ---------------- global scratch (fp16, row-major [m][K]) ----------------
__device__ __half g_xh [(size_t)MTOT * 64];
__device__ __half g_xl [(size_t)MTOT * 64];
__device__ __half g_embh[(size_t)MTOT * DM];
__device__ __half g_embl[(size_t)MTOT * DM];
__device__ __half g_h1 [(size_t)MTOT * DM];
__device__ __half g_w1[DM * DM];          // [n][k]
__device__ __half g_w2[DM * DM];          // [n][k]
__device__ __half g_cw[DM * 64];          // [n][64]

// ---------------- helpers ----------------
__device__ __forceinline__ uint32_t smem_u32(const void* p) {
    uint32_t a;
    asm("{ .reg .u64 t; cvta.to.shared.u64 t, %1; cvt.u32.u64 %0, t; }" : "=r"(a) : "l"(p));
    return a;
}
__device__ __forceinline__ void cp16(uint32_t s, const void* g) {
    asm volatile("cp.async.cg.shared.global [%0], [%1], 16;" ::
                 "r"(s), "l"(__cvta_generic_to_global(g)));
}
#define CP_COMMIT() asm volatile("cp.async.commit_group;" ::: "memory")
template <int N>
__device__ __forceinline__ void cp_wait() {
    asm volatile("cp.async.wait_group %0;" :: "n"(N) : "memory");
}

__device__ __forceinline__ void ldmat4(uint32_t (&r)[4], uint32_t a) {
    asm volatile("ldmatrix.sync.aligned.m8n8.x4.shared.b16 {%0,%1,%2,%3}, [%4];"
                 : "=r"(r[0]), "=r"(r[1]), "=r"(r[2]), "=r"(r[3]) : "r"(a));
}
__device__ __forceinline__ void mma16816(float (&d)[4], const uint32_t* a, uint32_t b0, uint32_t b1) {
    asm volatile("mma.sync.aligned.m16n8k16.row.col.f32.f16.f16.f32 "
                 "{%0,%1,%2,%3},{%4,%5,%6,%7},{%8,%9},{%0,%1,%2,%3};"
                 : "+f"(d[0]), "+f"(d[1]), "+f"(d[2]), "+f"(d[3])
                 : "r"(a[0]), "r"(a[1]), "r"(a[2]), "r"(a[3]), "r"(b0), "r"(b1));
}
__device__ __forceinline__ void split_hl(float v, __half& h, __half& l) {
    h = __float2half(v);
    l = __float2half(v - __half2float(h));
}

// ---- one BK=32 chunk; NPASS A planes at [0..NPASS-1]*PLANE, B at NPASS*PLANE ----
template <int NPASS>
__device__ __forceinline__ void compute_chunk(uint32_t stg, int wm, int wn, int lane,
                                              float (&acc)[2][8][4]) {
    uint32_t r16 = (uint32_t)(lane & 15) * PITCH;
    uint32_t khalf = (uint32_t)(lane >> 4) * 16;
#pragma unroll
    for (int k16 = 0; k16 < 2; k16++) {
        uint32_t kc = khalf + (uint32_t)(k16 * 32);
        uint32_t af[2][NPASS][4];
#pragma unroll
        for (int mf = 0; mf < 2; mf++) {
            uint32_t ao = (uint32_t)(wm + mf * 16) * PITCH + r16 + kc;
#pragma unroll
            for (int p = 0; p < NPASS; p++) ldmat4(af[mf][p], stg + p * PLANE + ao);
        }
#pragma unroll
        for (int ng = 0; ng < 4; ng++) {
            uint32_t bo = (uint32_t)(wn + ng * 16) * PITCH + r16 + kc;
            uint32_t bf[4];
            ldmat4(bf, stg + NPASS * PLANE + bo);
#pragma unroll
            for (int mf = 0; mf < 2; mf++)
#pragma unroll
                for (int sub = 0; sub < 2; sub++) {
                    int nf = ng * 2 + sub;
                    uint32_t b0 = sub ? bf[1] : bf[0];
                    uint32_t b1 = sub ? bf[3] : bf[2];
#pragma unroll
                    for (int p = 0; p < NPASS; p++)
                        mma16816(acc[mf][nf], af[mf][p], b0, b1);
                }
        }
    }
}

// ---- stage loader ----
template <int KD, int NPASS>
__device__ __forceinline__ void load_stage(uint32_t stg,
                                           const __half* __restrict__ Ah,
                                           const __half* __restrict__ Al,
                                           const __half* __restrict__ Bp,
                                           int m0, int n0, int k0, int tid) {
#pragma unroll
    for (int it = 0; it < 2; it++) {
        int idx = tid + it * 256;                  // 0..511
        int row = idx >> 2, c = idx & 3;
        uint32_t so = (uint32_t)row * PITCH + (uint32_t)c * 16;
        size_t ga = (size_t)(m0 + row) * KD + k0 + c * 8;
        size_t gb = (size_t)(n0 + row) * KD + k0 + c * 8;
        cp16(stg + so, Ah + ga);
        if (NPASS == 2) cp16(stg + PLANE + so, Al + ga);
        cp16(stg + NPASS * PLANE + so, Bp + gb);
    }
}

// ---------------- merged prep ----------------
#define NW (DM * DM)             // 589824
#define NCW (DM * 64)            // 49152
#define NX ((size_t)MTOT * 64)   // 11010048
__global__ void k_prep(const float* __restrict__ w1, const float* __restrict__ w2,
                       const float* __restrict__ cw, const float* __restrict__ x) {
    size_t gid = (size_t)blockIdx.x * 256 + threadIdx.x;
    if (gid < NX) {
        int m = (int)(gid >> 6), k = (int)(gid & 63);
        int seq = m >> 7, r = m & 127;
        float v = 0.f;
        if (k < 48) {
            int t = k >> 4, i = k & 15;
            int pp = (r + t + 127) & 127;
            int j = pp * 8 + i;
            if (j > 1023) j = 1023;
            v = x[(size_t)seq * 1024 + j];
        }
        __half h, l;
        split_hl(v, h, l);
        g_xh[gid] = h;
        g_xl[gid] = l;
        return;
    }
    size_t g2 = gid - NX;
    if (g2 < 2 * NW) {
        const float* w = (g2 < NW) ? w1 : w2;
        __half* t = (g2 < NW) ? g_w1 : g_w2;
        int i = (int)(g2 % NW);
        int k = i / DM, n = i - k * DM;
        t[(size_t)n * DM + k] = __float2half(w[i]);
        return;
    }
    size_t g3 = g2 - 2 * NW;
    if (g3 < NCW) {
        int n = (int)(g3 >> 6), k = (int)(g3 & 63);
        float v = 0.f;
        if (k < 48) { int i = k & 15, t = k >> 4; v = cw[n * 48 + i * 3 + t]; }
        g_cw[g3] = __float2half(v);
    }
}

// ---------------- unified GEMM ----------------
// MODE 0: relu(A@B + bias) -> single fp16 plane (h1), NPASS=2
// MODE 1: A@B + bias + (embh+embl) -> fp32 out, NPASS=1
// MODE 2: A@B -> hi/lo fp16 planes (embed), NPASS=2
template <int MODE, int KD, int NPASS, int NSTAGE>
__global__ void __launch_bounds__(256, 2) k_gemm(const __half* __restrict__ Ah,
                                                 const __half* __restrict__ Al,
                                                 const __half* __restrict__ Bp,
                                                 const float* __restrict__ bias,
                                                 __half* __restrict__ Oh,
                                                 __half* __restrict__ Ol,
                                                 float* __restrict__ outF) {
    constexpr int NCH = KD / 32;
    constexpr uint32_t STGB = (NPASS + 1) * PLANE;
    extern __shared__ __align__(128) char smem[];
    uint32_t sb = smem_u32(smem);
    int tid = threadIdx.x, wid = tid >> 5, lane = tid & 31;
    int wm = (wid & 3) * 32, wn = (wid >> 2) * 64;
    int m0 = blockIdx.y * 128, n0 = blockIdx.x * 128;

    float acc[2][8][4];
#pragma unroll
    for (int a = 0; a < 2; a++)
#pragma unroll
        for (int b = 0; b < 8; b++)
#pragma unroll
            for (int c = 0; c < 4; c++) acc[a][b][c] = 0.f;

#pragma unroll
    for (int s = 0; s < NSTAGE; s++) {
        if (s < NCH) load_stage<KD, NPASS>(sb + (uint32_t)s * STGB, Ah, Al, Bp, m0, n0, s * 32, tid);
        CP_COMMIT();
    }

#pragma unroll 1
    for (int c = 0; c < NCH; c++) {
        cp_wait<NSTAGE - 1>();
        __syncthreads();
        uint32_t stg = sb + (uint32_t)(c % NSTAGE) * STGB;
        compute_chunk<NPASS>(stg, wm, wn, lane, acc);
        __syncthreads();
        if (c + NSTAGE < NCH)
            load_stage<KD, NPASS>(stg, Ah, Al, Bp, m0, n0, (c + NSTAGE) * 32, tid);
        CP_COMMIT();
    }

    // ---- smem-staged epilogue ----
    int rin = lane >> 2, colp = (lane & 3) * 2;
    if (MODE == 1) {
        float* smf = (float*)smem;                 // pitch 132 floats
#pragma unroll
        for (int mf = 0; mf < 2; mf++)
#pragma unroll
            for (int nf = 0; nf < 8; nf++) {
                int cn = wn + nf * 8 + colp;
                float b0 = bias[n0 + cn], b1 = bias[n0 + cn + 1];
#pragma unroll
                for (int half = 0; half < 2; half++) {
                    int rr = wm + mf * 16 + rin + half * 8;
                    float2 v;
                    v.x = acc[mf][nf][half * 2] + b0;
                    v.y = acc[mf][nf][half * 2 + 1] + b1;
                    *(float2*)(smf + (size_t)rr * 132 + cn) = v;
                }
            }
        __syncthreads();
        for (int i = tid; i < 8192; i += 256) {
            int r = i >> 6, c = i & 63;
            float2 v = *(float2*)(smf + (size_t)r * 132 + c * 2);
            size_t o = (size_t)(m0 + r) * DM + n0 + c * 2;
            __half2 rh = *(const __half2*)(g_embh + o);
            __half2 rl = *(const __half2*)(g_embl + o);
            float2 fh = __half22float2(rh);
            float2 fl = __half22float2(rl);
            v.x += fh.x + fl.x;
            v.y += fh.y + fl.y;
            *(float2*)(outF + o) = v;
        }
    } else if (MODE == 0) {
        char* smc = smem;                          // one fp16 plane, pitch 272B
#pragma unroll
        for (int mf = 0; mf < 2; mf++)
#pragma unroll
            for (int nf = 0; nf < 8; nf++) {
                int cn = wn + nf * 8 + colp;
                float b0 = bias[n0 + cn], b1 = bias[n0 + cn + 1];
#pragma unroll
                for (int half = 0; half < 2; half++) {
                    int rr = wm + mf * 16 + rin + half * 8;
                    float v0 = fmaxf(acc[mf][nf][half * 2] + b0, 0.f);
                    float v1 = fmaxf(acc[mf][nf][half * 2 + 1] + b1, 0.f);
                    __half2 hp;
                    hp.x = __float2half(v0);
                    hp.y = __float2half(v1);
                    *(__half2*)(smc + (size_t)rr * 272 + cn * 2) = hp;
                }
            }
        __syncthreads();
        for (int i = tid; i < 2048; i += 256) {
            int r = i >> 4, c = i & 15;
            uint4 vh = *(uint4*)(smc + (size_t)r * 272 + c * 16);
            size_t o = (size_t)(m0 + r) * DM + n0 + c * 8;
            *(uint4*)(Oh + o) = vh;
        }
    } else {
        char* smc = smem;                          // two fp16 planes, pitch 272B
#pragma unroll
        for (int mf = 0; mf < 2; mf++)
#pragma unroll
            for (int nf = 0; nf < 8; nf++) {
                int cn = wn + nf * 8 + colp;
#pragma unroll
                for (int half = 0; half < 2; half++) {
                    int rr = wm + mf * 16 + rin + half * 8;
                    float v0 = acc[mf][nf][half * 2];
                    float v1 = acc[mf][nf][half * 2 + 1];
                    __half2 hp, lp;
                    split_hl(v0, hp.x, lp.x);
                    split_hl(v1, hp.y, lp.y);
                    *(__half2*)(smc + (size_t)rr * 272 + cn * 2) = hp;
                    *(__half2*)(smc + 34816 + (size_t)rr * 272 + cn * 2) = lp;
                }
            }
        __syncthreads();
        for (int i = tid; i < 2048; i += 256) {
            int r = i >> 4, c = i & 15;
            uint4 vh = *(uint4*)(smc + (size_t)r * 272 + c * 16);
            uint4 vl = *(uint4*)(smc + 34816 + (size_t)r * 272 + c * 16);
            size_t o = (size_t)(m0 + r) * DM + n0 + c * 8;
            *(uint4*)(Oh + o) = vh;
            *(uint4*)(Ol + o) = vl;
        }
    }
}

// ---------------- launcher ----------------
extern "C" void kernel_launch(void* const* d_in, const int* in_sizes, int n_in,
                              void* d_out, int out_size) {
    (void)in_sizes; (void)n_in; (void)out_size;
    const float* x      = (const float*)d_in[0];
    const float* conv_w = (const float*)d_in[1];
    const float* w1     = (const float*)d_in[2];
    const float* b1     = (const float*)d_in[3];
    const float* w2     = (const float*)d_in[4];
    const float* b2     = (const float*)d_in[5];
    float* out = (float*)d_out;

    __half *xh, *xl, *embh, *embl, *h1p, *w1p, *w2p, *cwp;
    cudaGetSymbolAddress((void**)&xh, g_xh);
    cudaGetSymbolAddress((void**)&xl, g_xl);
    cudaGetSymbolAddress((void**)&embh, g_embh);
    cudaGetSymbolAddress((void**)&embl, g_embl);
    cudaGetSymbolAddress((void**)&h1p, g_h1);
    cudaGetSymbolAddress((void**)&w1p, g_w1);
    cudaGetSymbolAddress((void**)&w2p, g_w2);
    cudaGetSymbolAddress((void**)&cwp, g_cw);

    cudaFuncSetAttribute((const void*)k_gemm<2, 64, 2, NST2>,
                         cudaFuncAttributeMaxDynamicSharedMemorySize, SMEM_G2);
    cudaFuncSetAttribute((const void*)k_gemm<0, 768, 2, NST2>,
                         cudaFuncAttributeMaxDynamicSharedMemorySize, SMEM_G2);
    cudaFuncSetAttribute((const void*)k_gemm<1, 768, 1, NST1>,
                         cudaFuncAttributeMaxDynamicSharedMemorySize, SMEM_G1);

    size_t total = NX + 2 * (size_t)NW + NCW;
    k_prep<<<(unsigned)((total + 255) / 256), 256>>>(w1, w2, conv_w, x);

    dim3 grid(NT_TILES, MT_TILES);
    k_gemm<2, 64, 2, NST2><<<grid, 256, SMEM_G2>>>(xh, xl, cwp, nullptr, embh, embl, nullptr);
    k_gemm<0, 768, 2, NST2><<<grid, 256, SMEM_G2>>>(embh, embl, w1p, b1, h1p, nullptr, nullptr);
    k_gemm<1, 768, 1, NST1><<<grid, 256, SMEM_G1>>>(h1p, nullptr, w2p, b2, nullptr, nullptr, out);
}

// round 7
// speedup vs baseline: 4.9483x; 1.2985x over previous
#include <cuda_runtime.h>
#include <cuda_fp16.h>
#include <cstdint>

#define MTOT 172032
#define DM   768
#define MT_TILES 1344
#define NT_TILES 6

#define PITCH 80                 // bytes per 32-fp16 row (conflict-free ldmatrix)
#define PLANE (128 * PITCH)      // 10240

// 2-pass kernel (embed): 3 planes/stage, 3 stages
#define STGB2  (3 * PLANE)       // 30720
#define NST2   3
#define SMEM_G2 (NST2 * STGB2)   // 92160
// 1-pass kernels: 2 planes/stage, 4 stages
#define STGB1  (2 * PLANE)       // 20480
#define NST1   4
#define SMEM_G1 (NST1 * STGB1)   // 81920 (also covers 67584B fp32 epilogue)

// ---------------- global scratch (fp16, row-major [m][K]) ----------------
__device__ __half g_xh [(size_t)MTOT * 64];
__device__ __half g_xl [(size_t)MTOT * 64];
__device__ __half g_embh[(size_t)MTOT * DM];
__device__ __half g_embl[(size_t)MTOT * DM];
__device__ __half g_h1 [(size_t)MTOT * DM];
__device__ __half g_w1[DM * DM];          // [n][k]
__device__ __half g_w2[DM * DM];          // [n][k]
__device__ __half g_cw[DM * 64];          // [n][64]

// ---------------- helpers ----------------
__device__ __forceinline__ uint32_t smem_u32(const void* p) {
    uint32_t a;
    asm("{ .reg .u64 t; cvta.to.shared.u64 t, %1; cvt.u32.u64 %0, t; }" : "=r"(a) : "l"(p));
    return a;
}
__device__ __forceinline__ void cp16(uint32_t s, const void* g) {
    asm volatile("cp.async.cg.shared.global [%0], [%1], 16;" ::
                 "r"(s), "l"(__cvta_generic_to_global(g)));
}
#define CP_COMMIT() asm volatile("cp.async.commit_group;" ::: "memory")
template <int N>
__device__ __forceinline__ void cp_wait() {
    asm volatile("cp.async.wait_group %0;" :: "n"(N) : "memory");
}

__device__ __forceinline__ void ldmat4(uint32_t (&r)[4], uint32_t a) {
    asm volatile("ldmatrix.sync.aligned.m8n8.x4.shared.b16 {%0,%1,%2,%3}, [%4];"
                 : "=r"(r[0]), "=r"(r[1]), "=r"(r[2]), "=r"(r[3]) : "r"(a));
}
__device__ __forceinline__ void mma16816(float (&d)[4], const uint32_t* a, uint32_t b0, uint32_t b1) {
    asm volatile("mma.sync.aligned.m16n8k16.row.col.f32.f16.f16.f32 "
                 "{%0,%1,%2,%3},{%4,%5,%6,%7},{%8,%9},{%0,%1,%2,%3};"
                 : "+f"(d[0]), "+f"(d[1]), "+f"(d[2]), "+f"(d[3])
                 : "r"(a[0]), "r"(a[1]), "r"(a[2]), "r"(a[3]), "r"(b0), "r"(b1));
}
__device__ __forceinline__ void split_hl(float v, __half& h, __half& l) {
    h = __float2half(v);
    l = __float2half(v - __half2float(h));
}

// ---- one BK=32 chunk; NPASS A planes at [0..NPASS-1]*PLANE, B at NPASS*PLANE ----
template <int NPASS>
__device__ __forceinline__ void compute_chunk(uint32_t stg, int wm, int wn, int lane,
                                              float (&acc)[2][8][4]) {
    uint32_t r16 = (uint32_t)(lane & 15) * PITCH;
    uint32_t khalf = (uint32_t)(lane >> 4) * 16;
#pragma unroll
    for (int k16 = 0; k16 < 2; k16++) {
        uint32_t kc = khalf + (uint32_t)(k16 * 32);
        uint32_t af[2][NPASS][4];
#pragma unroll
        for (int mf = 0; mf < 2; mf++) {
            uint32_t ao = (uint32_t)(wm + mf * 16) * PITCH + r16 + kc;
#pragma unroll
            for (int p = 0; p < NPASS; p++) ldmat4(af[mf][p], stg + p * PLANE + ao);
        }
#pragma unroll
        for (int ng = 0; ng < 4; ng++) {
            uint32_t bo = (uint32_t)(wn + ng * 16) * PITCH + r16 + kc;
            uint32_t bf[4];
            ldmat4(bf, stg + NPASS * PLANE + bo);
#pragma unroll
            for (int mf = 0; mf < 2; mf++)
#pragma unroll
                for (int sub = 0; sub < 2; sub++) {
                    int nf = ng * 2 + sub;
                    uint32_t b0 = sub ? bf[1] : bf[0];
                    uint32_t b1 = sub ? bf[3] : bf[2];
#pragma unroll
                    for (int p = 0; p < NPASS; p++)
                        mma16816(acc[mf][nf], af[mf][p], b0, b1);
                }
        }
    }
}

// ---- stage loader ----
template <int KD, int NPASS>
__device__ __forceinline__ void load_stage(uint32_t stg,
                                           const __half* __restrict__ Ah,
                                           const __half* __restrict__ Al,
                                           const __half* __restrict__ Bp,
                                           int m0, int n0, int k0, int tid) {
#pragma unroll
    for (int it = 0; it < 2; it++) {
        int idx = tid + it * 256;                  // 0..511
        int row = idx >> 2, c = idx & 3;
        uint32_t so = (uint32_t)row * PITCH + (uint32_t)c * 16;
        size_t ga = (size_t)(m0 + row) * KD + k0 + c * 8;
        size_t gb = (size_t)(n0 + row) * KD + k0 + c * 8;
        cp16(stg + so, Ah + ga);
        if (NPASS == 2) cp16(stg + PLANE + so, Al + ga);
        cp16(stg + NPASS * PLANE + so, Bp + gb);
    }
}

// ---------------- merged prep ----------------
#define NW (DM * DM)             // 589824
#define NCW (DM * 64)            // 49152
#define NX ((size_t)MTOT * 64)   // 11010048
__global__ void k_prep(const float* __restrict__ w1, const float* __restrict__ w2,
                       const float* __restrict__ cw, const float* __restrict__ x) {
    size_t gid = (size_t)blockIdx.x * 256 + threadIdx.x;
    if (gid < NX) {
        int m = (int)(gid >> 6), k = (int)(gid & 63);
        int seq = m >> 7, r = m & 127;
        float v = 0.f;
        if (k < 48) {
            int t = k >> 4, i = k & 15;
            int pp = (r + t + 127) & 127;
            int j = pp * 8 + i;
            if (j > 1023) j = 1023;
            v = x[(size_t)seq * 1024 + j];
        }
        __half h, l;
        split_hl(v, h, l);
        g_xh[gid] = h;
        g_xl[gid] = l;
        return;
    }
    size_t g2 = gid - NX;
    if (g2 < 2 * NW) {
        const float* w = (g2 < NW) ? w1 : w2;
        __half* t = (g2 < NW) ? g_w1 : g_w2;
        int i = (int)(g2 % NW);
        int k = i / DM, n = i - k * DM;
        t[(size_t)n * DM + k] = __float2half(w[i]);
        return;
    }
    size_t g3 = g2 - 2 * NW;
    if (g3 < NCW) {
        int n = (int)(g3 >> 6), k = (int)(g3 & 63);
        float v = 0.f;
        if (k < 48) { int i = k & 15, t = k >> 4; v = cw[n * 48 + i * 3 + t]; }
        g_cw[g3] = __float2half(v);
    }
}

// ---------------- unified GEMM ----------------
// MODE 0: relu(A@B + bias) -> single fp16 plane (h1)
// MODE 1: A@B + bias + (embh+embl) -> fp32 out
// MODE 2: A@B -> hi/lo fp16 planes (embed)
template <int MODE, int KD, int NPASS, int NSTAGE>
__global__ void __launch_bounds__(256, 2) k_gemm(const __half* __restrict__ Ah,
                                                 const __half* __restrict__ Al,
                                                 const __half* __restrict__ Bp,
                                                 const float* __restrict__ bias,
                                                 __half* __restrict__ Oh,
                                                 __half* __restrict__ Ol,
                                                 float* __restrict__ outF) {
    constexpr int NCH = KD / 32;
    constexpr uint32_t STGB = (NPASS + 1) * PLANE;
    extern __shared__ __align__(128) char smem[];
    uint32_t sb = smem_u32(smem);
    int tid = threadIdx.x, wid = tid >> 5, lane = tid & 31;
    int wm = (wid & 3) * 32, wn = (wid >> 2) * 64;
    int m0 = blockIdx.y * 128, n0 = blockIdx.x * 128;

    float acc[2][8][4];
#pragma unroll
    for (int a = 0; a < 2; a++)
#pragma unroll
        for (int b = 0; b < 8; b++)
#pragma unroll
            for (int c = 0; c < 4; c++) acc[a][b][c] = 0.f;

#pragma unroll
    for (int s = 0; s < NSTAGE; s++) {
        if (s < NCH) load_stage<KD, NPASS>(sb + (uint32_t)s * STGB, Ah, Al, Bp, m0, n0, s * 32, tid);
        CP_COMMIT();
    }

#pragma unroll 1
    for (int c = 0; c < NCH; c++) {
        cp_wait<NSTAGE - 1>();
        __syncthreads();
        uint32_t stg = sb + (uint32_t)(c % NSTAGE) * STGB;
        compute_chunk<NPASS>(stg, wm, wn, lane, acc);
        __syncthreads();
        if (c + NSTAGE < NCH)
            load_stage<KD, NPASS>(stg, Ah, Al, Bp, m0, n0, (c + NSTAGE) * 32, tid);
        CP_COMMIT();
    }

    // ---- smem-staged epilogue ----
    int rin = lane >> 2, colp = (lane & 3) * 2;
    if (MODE == 1) {
        float* smf = (float*)smem;                 // pitch 132 floats
#pragma unroll
        for (int mf = 0; mf < 2; mf++)
#pragma unroll
            for (int nf = 0; nf < 8; nf++) {
                int cn = wn + nf * 8 + colp;
                float b0 = bias[n0 + cn], b1 = bias[n0 + cn + 1];
#pragma unroll
                for (int half = 0; half < 2; half++) {
                    int rr = wm + mf * 16 + rin + half * 8;
                    float2 v;
                    v.x = acc[mf][nf][half * 2] + b0;
                    v.y = acc[mf][nf][half * 2 + 1] + b1;
                    *(float2*)(smf + (size_t)rr * 132 + cn) = v;
                }
            }
        __syncthreads();
        for (int i = tid; i < 8192; i += 256) {
            int r = i >> 6, c = i & 63;
            float2 v = *(float2*)(smf + (size_t)r * 132 + c * 2);
            size_t o = (size_t)(m0 + r) * DM + n0 + c * 2;
            __half2 rh = *(const __half2*)(g_embh + o);
            __half2 rl = *(const __half2*)(g_embl + o);
            float2 fh = __half22float2(rh);
            float2 fl = __half22float2(rl);
            v.x += fh.x + fl.x;
            v.y += fh.y + fl.y;
            *(float2*)(outF + o) = v;
        }
    } else if (MODE == 0) {
        char* smc = smem;                          // one fp16 plane, pitch 272B
#pragma unroll
        for (int mf = 0; mf < 2; mf++)
#pragma unroll
            for (int nf = 0; nf < 8; nf++) {
                int cn = wn + nf * 8 + colp;
                float b0 = bias[n0 + cn], b1 = bias[n0 + cn + 1];
#pragma unroll
                for (int half = 0; half < 2; half++) {
                    int rr = wm + mf * 16 + rin + half * 8;
                    float v0 = fmaxf(acc[mf][nf][half * 2] + b0, 0.f);
                    float v1 = fmaxf(acc[mf][nf][half * 2 + 1] + b1, 0.f);
                    __half2 hp;
                    hp.x = __float2half(v0);
                    hp.y = __float2half(v1);
                    *(__half2*)(smc + (size_t)rr * 272 + cn * 2) = hp;
                }
            }
        __syncthreads();
        for (int i = tid; i < 2048; i += 256) {
            int r = i >> 4, c = i & 15;
            uint4 vh = *(uint4*)(smc + (size_t)r * 272 + c * 16);
            size_t o = (size_t)(m0 + r) * DM + n0 + c * 8;
            *(uint4*)(Oh + o) = vh;
        }
    } else {
        char* smc = smem;                          // two fp16 planes, pitch 272B
#pragma unroll
        for (int mf = 0; mf < 2; mf++)
#pragma unroll
            for (int nf = 0; nf < 8; nf++) {
                int cn = wn + nf * 8 + colp;
#pragma unroll
                for (int half = 0; half < 2; half++) {
                    int rr = wm + mf * 16 + rin + half * 8;
                    float v0 = acc[mf][nf][half * 2];
                    float v1 = acc[mf][nf][half * 2 + 1];
                    __half2 hp, lp;
                    split_hl(v0, hp.x, lp.x);
                    split_hl(v1, hp.y, lp.y);
                    *(__half2*)(smc + (size_t)rr * 272 + cn * 2) = hp;
                    *(__half2*)(smc + 34816 + (size_t)rr * 272 + cn * 2) = lp;
                }
            }
        __syncthreads();
        for (int i = tid; i < 2048; i += 256) {
            int r = i >> 4, c = i & 15;
            uint4 vh = *(uint4*)(smc + (size_t)r * 272 + c * 16);
            uint4 vl = *(uint4*)(smc + 34816 + (size_t)r * 272 + c * 16);
            size_t o = (size_t)(m0 + r) * DM + n0 + c * 8;
            *(uint4*)(Oh + o) = vh;
            *(uint4*)(Ol + o) = vl;
        }
    }
}

// ---------------- launcher ----------------
extern "C" void kernel_launch(void* const* d_in, const int* in_sizes, int n_in,
                              void* d_out, int out_size) {
    (void)in_sizes; (void)n_in; (void)out_size;
    const float* x      = (const float*)d_in[0];
    const float* conv_w = (const float*)d_in[1];
    const float* w1     = (const float*)d_in[2];
    const float* b1     = (const float*)d_in[3];
    const float* w2     = (const float*)d_in[4];
    const float* b2     = (const float*)d_in[5];
    float* out = (float*)d_out;

    __half *xh, *xl, *embh, *embl, *h1p, *w1p, *w2p, *cwp;
    cudaGetSymbolAddress((void**)&xh, g_xh);
    cudaGetSymbolAddress((void**)&xl, g_xl);
    cudaGetSymbolAddress((void**)&embh, g_embh);
    cudaGetSymbolAddress((void**)&embl, g_embl);
    cudaGetSymbolAddress((void**)&h1p, g_h1);
    cudaGetSymbolAddress((void**)&w1p, g_w1);
    cudaGetSymbolAddress((void**)&w2p, g_w2);
    cudaGetSymbolAddress((void**)&cwp, g_cw);

    cudaFuncSetAttribute((const void*)k_gemm<2, 64, 2, NST2>,
                         cudaFuncAttributeMaxDynamicSharedMemorySize, SMEM_G2);
    cudaFuncSetAttribute((const void*)k_gemm<0, 768, 1, NST1>,
                         cudaFuncAttributeMaxDynamicSharedMemorySize, SMEM_G1);
    cudaFuncSetAttribute((const void*)k_gemm<1, 768, 1, NST1>,
                         cudaFuncAttributeMaxDynamicSharedMemorySize, SMEM_G1);

    size_t total = NX + 2 * (size_t)NW + NCW;
    k_prep<<<(unsigned)((total + 255) / 256), 256>>>(w1, w2, conv_w, x);

    dim3 grid(NT_TILES, MT_TILES);
    // embed: 2-pass (x hi/lo) x cw -> emb hi/lo (residual needs hi/lo precision)
    k_gemm<2, 64, 2, NST2><<<grid, 256, SMEM_G2>>>(xh, xl, cwp, nullptr, embh, embl, nullptr);
    // GEMM1: 1-pass (embh only) -> h1 fp16
    k_gemm<0, 768, 1, NST1><<<grid, 256, SMEM_G1>>>(embh, nullptr, w1p, b1, h1p, nullptr, nullptr);
    // GEMM2: 1-pass -> out fp32 (+ exact hi/lo residual)
    k_gemm<1, 768, 1, NST1><<<grid, 256, SMEM_G1>>>(h1p, nullptr, w2p, b2, nullptr, nullptr, out);
}